// round 2
// baseline (speedup 1.0000x reference)
#include <cuda_runtime.h>
#include <cuda_bf16.h>
#include <math.h>

// ---------------------------------------------------------------------------
// Problem constants (fixed by the dataset; runtime values checked to fit)
// ---------------------------------------------------------------------------
#define MAXN 100352          // >= N=100000, multiple of 1024 and 64
#define MAXE 1600000         // == E
#define IN_DIM 128
#define HID_DIM 128
#define OUT_DIM 64
#define BN_EPS 1e-5f

// ---------------------------------------------------------------------------
// Scratch (device globals; no runtime allocation allowed)
// ---------------------------------------------------------------------------
__device__ int    g_cnt_in [MAXN];
__device__ int    g_cnt_out[MAXN];
__device__ float  g_rs_in  [MAXN];
__device__ float  g_rs_out [MAXN];
__device__ int    g_rowp   [MAXN + 1];
__device__ int    g_cursor [MAXN];
__device__ int    g_csr    [MAXE];
__device__ int    g_bsum   [1024];

__device__ float  g_t1[(size_t)MAXN * HID_DIM];  // (h*rs_out)@W1
__device__ float  g_y1[(size_t)MAXN * HID_DIM];  // post-aggregation layer1 out
__device__ float  g_t2[(size_t)MAXN * OUT_DIM];  // (bnrelu(y1)*rs_out)@W2

__device__ double g_bnsum[HID_DIM];
__device__ double g_bnsq [HID_DIM];
__device__ float  g_A[HID_DIM];   // gamma * rsqrt(var+eps)
__device__ float  g_B[HID_DIM];   // beta - mean * A

// ---------------------------------------------------------------------------
// 1. Zero counters + BN accumulators
// ---------------------------------------------------------------------------
__global__ void zero_kernel(int N) {
    int i = blockIdx.x * blockDim.x + threadIdx.x;
    if (i < N) { g_cnt_in[i] = 0; g_cnt_out[i] = 0; }
    if (i < HID_DIM) { g_bnsum[i] = 0.0; g_bnsq[i] = 0.0; }
}

// ---------------------------------------------------------------------------
// 2. Degree histograms
// ---------------------------------------------------------------------------
__global__ void hist_kernel(const int* __restrict__ src,
                            const int* __restrict__ dst, int E) {
    int e = blockIdx.x * blockDim.x + threadIdx.x;
    if (e < E) {
        atomicAdd(&g_cnt_out[src[e]], 1);
        atomicAdd(&g_cnt_in [dst[e]], 1);
    }
}

// ---------------------------------------------------------------------------
// 3. rsqrt of clamped degrees
// ---------------------------------------------------------------------------
__global__ void rsqrt_kernel(int N) {
    int i = blockIdx.x * blockDim.x + threadIdx.x;
    if (i < N) {
        int ci = g_cnt_in[i];  if (ci < 1) ci = 1;
        int co = g_cnt_out[i]; if (co < 1) co = 1;
        g_rs_in[i]  = rsqrtf((float)ci);
        g_rs_out[i] = rsqrtf((float)co);
    }
}

// ---------------------------------------------------------------------------
// 4-6. Exclusive scan of in-degrees -> row_ptr (3-phase block scan)
// ---------------------------------------------------------------------------
__global__ void scan_a_kernel(int N) {
    __shared__ int sh[1024];
    int tid = threadIdx.x;
    int i = blockIdx.x * 1024 + tid;
    int v = (i < N) ? g_cnt_in[i] : 0;
    sh[tid] = v;
    __syncthreads();
    for (int off = 1; off < 1024; off <<= 1) {
        int t = 0;
        if (tid >= off) t = sh[tid - off];
        __syncthreads();
        sh[tid] += t;
        __syncthreads();
    }
    if (i < N) g_rowp[i] = sh[tid] - v;     // exclusive within block
    if (tid == 1023) g_bsum[blockIdx.x] = sh[tid];
}

__global__ void scan_b_kernel(int nb) {
    __shared__ int sh[1024];
    int tid = threadIdx.x;
    int v = (tid < nb) ? g_bsum[tid] : 0;
    sh[tid] = v;
    __syncthreads();
    for (int off = 1; off < 1024; off <<= 1) {
        int t = 0;
        if (tid >= off) t = sh[tid - off];
        __syncthreads();
        sh[tid] += t;
        __syncthreads();
    }
    if (tid < nb) g_bsum[tid] = sh[tid] - v; // exclusive block offsets
}

__global__ void scan_c_kernel(int N, int E) {
    int i = blockIdx.x * 1024 + threadIdx.x;
    if (i < N) {
        int v = g_rowp[i] + g_bsum[blockIdx.x];
        g_rowp[i] = v;
        g_cursor[i] = v;
    }
    if (i == 0) g_rowp[N] = E;
}

// ---------------------------------------------------------------------------
// 7. CSR fill (dst-bucketed list of src indices)
// ---------------------------------------------------------------------------
__global__ void csr_fill_kernel(const int* __restrict__ src,
                                const int* __restrict__ dst, int E) {
    int e = blockIdx.x * blockDim.x + threadIdx.x;
    if (e < E) {
        int d = dst[e];
        int p = atomicAdd(&g_cursor[d], 1);
        g_csr[p] = src[e];
    }
}

// ---------------------------------------------------------------------------
// 8. GEMM1: t1 = (h * rs_out[:,None]) @ W1     [N,128]@[128,128]
//    256 threads, 64 rows/block. W1 + scaled X tile in dyn smem.
//    Each thread: 8 rows x 4 cols (warp rows uniform -> broadcast LDS).
// ---------------------------------------------------------------------------
__global__ void gemm1_kernel(const float* __restrict__ h,
                             const float* __restrict__ W, int N) {
    extern __shared__ float smem[];
    float* Ws = smem;                 // 128*128
    float* Xs = smem + 128 * 128;     // 64*128
    int tid = threadIdx.x;

    const float4* W4 = (const float4*)W;
    float4* Ws4 = (float4*)Ws;
    #pragma unroll 4
    for (int i = tid; i < 128 * 128 / 4; i += 256) Ws4[i] = W4[i];

    int row0 = blockIdx.x * 64;
    float4* Xs4 = (float4*)Xs;
    for (int i = tid; i < 64 * 32; i += 256) {
        int r = i >> 5, c = i & 31;
        int row = row0 + r;
        float4 v = make_float4(0.f, 0.f, 0.f, 0.f);
        if (row < N) {
            v = ((const float4*)h)[(size_t)row * 32 + c];
            float s = g_rs_out[row];
            v.x *= s; v.y *= s; v.z *= s; v.w *= s;
        }
        Xs4[i] = v;
    }
    __syncthreads();

    int lane  = tid & 31;
    int rbase = (tid >> 5) * 8;
    float acc[8][4];
    #pragma unroll
    for (int r = 0; r < 8; r++)
        acc[r][0] = acc[r][1] = acc[r][2] = acc[r][3] = 0.f;

    for (int k = 0; k < 128; k += 4) {
        float4 xv[8];
        #pragma unroll
        for (int r = 0; r < 8; r++)
            xv[r] = *(const float4*)&Xs[(rbase + r) * 128 + k];
        #pragma unroll
        for (int kk = 0; kk < 4; kk++) {
            float4 wv = *(const float4*)&Ws[(k + kk) * 128 + lane * 4];
            #pragma unroll
            for (int r = 0; r < 8; r++) {
                float x = (kk == 0) ? xv[r].x : (kk == 1) ? xv[r].y
                        : (kk == 2) ? xv[r].z : xv[r].w;
                acc[r][0] = fmaf(x, wv.x, acc[r][0]);
                acc[r][1] = fmaf(x, wv.y, acc[r][1]);
                acc[r][2] = fmaf(x, wv.z, acc[r][2]);
                acc[r][3] = fmaf(x, wv.w, acc[r][3]);
            }
        }
    }
    #pragma unroll
    for (int r = 0; r < 8; r++) {
        int row = row0 + rbase + r;
        if (row < N)
            ((float4*)g_t1)[(size_t)row * 32 + lane] =
                make_float4(acc[r][0], acc[r][1], acc[r][2], acc[r][3]);
    }
}

// ---------------------------------------------------------------------------
// 9. SpMM1: y1[i] = (sum_{e in row i} t1[csr[e]]) * rs_in[i] + b1
//    Warp-per-node, lane covers 4 contiguous cols (float4).
//    4 independent accumulation chains per lane (MLP=4) to cover L2 latency.
//    Fused BN statistics (double) per lane -> block smem -> global atomics.
// ---------------------------------------------------------------------------
__global__ void spmm1_kernel(const float* __restrict__ b1, int N) {
    __shared__ double s_sum[HID_DIM];
    __shared__ double s_sq [HID_DIM];
    int tid = threadIdx.x;
    if (tid < HID_DIM) { s_sum[tid] = 0.0; s_sq[tid] = 0.0; }
    __syncthreads();

    int lane = tid & 31;
    int gw = (blockIdx.x * blockDim.x + tid) >> 5;
    int nw = (gridDim.x * blockDim.x) >> 5;

    const float4* __restrict__ t14 = (const float4*)g_t1;
    float4 bb = ((const float4*)b1)[lane];

    double ls0 = 0, ls1 = 0, ls2 = 0, ls3 = 0;
    double lq0 = 0, lq1 = 0, lq2 = 0, lq3 = 0;

    for (int i = gw; i < N; i += nw) {
        int beg = g_rowp[i], end = g_rowp[i + 1];
        float4 a0 = make_float4(0.f, 0.f, 0.f, 0.f);
        float4 a1 = make_float4(0.f, 0.f, 0.f, 0.f);
        float4 a2 = make_float4(0.f, 0.f, 0.f, 0.f);
        float4 a3 = make_float4(0.f, 0.f, 0.f, 0.f);
        int e = beg;
        for (; e + 3 < end; e += 4) {
            // indices first (sequential, L1/L2-hot) so the 4 gathers issue
            // back-to-back with no inter-dependency
            int s0 = g_csr[e], s1 = g_csr[e + 1];
            int s2 = g_csr[e + 2], s3 = g_csr[e + 3];
            float4 v0 = t14[(size_t)s0 * 32 + lane];
            float4 v1 = t14[(size_t)s1 * 32 + lane];
            float4 v2 = t14[(size_t)s2 * 32 + lane];
            float4 v3 = t14[(size_t)s3 * 32 + lane];
            a0.x += v0.x; a0.y += v0.y; a0.z += v0.z; a0.w += v0.w;
            a1.x += v1.x; a1.y += v1.y; a1.z += v1.z; a1.w += v1.w;
            a2.x += v2.x; a2.y += v2.y; a2.z += v2.z; a2.w += v2.w;
            a3.x += v3.x; a3.y += v3.y; a3.z += v3.z; a3.w += v3.w;
        }
        for (; e < end; e++) {
            int s0 = g_csr[e];
            float4 v0 = t14[(size_t)s0 * 32 + lane];
            a0.x += v0.x; a0.y += v0.y; a0.z += v0.z; a0.w += v0.w;
        }
        float r = g_rs_in[i];
        float4 y;
        y.x = ((a0.x + a1.x) + (a2.x + a3.x)) * r + bb.x;
        y.y = ((a0.y + a1.y) + (a2.y + a3.y)) * r + bb.y;
        y.z = ((a0.z + a1.z) + (a2.z + a3.z)) * r + bb.z;
        y.w = ((a0.w + a1.w) + (a2.w + a3.w)) * r + bb.w;
        ((float4*)g_y1)[(size_t)i * 32 + lane] = y;

        ls0 += y.x; lq0 += (double)y.x * y.x;
        ls1 += y.y; lq1 += (double)y.y * y.y;
        ls2 += y.z; lq2 += (double)y.z * y.z;
        ls3 += y.w; lq3 += (double)y.w * y.w;
    }
    int c = lane * 4;
    atomicAdd(&s_sum[c + 0], ls0); atomicAdd(&s_sq[c + 0], lq0);
    atomicAdd(&s_sum[c + 1], ls1); atomicAdd(&s_sq[c + 1], lq1);
    atomicAdd(&s_sum[c + 2], ls2); atomicAdd(&s_sq[c + 2], lq2);
    atomicAdd(&s_sum[c + 3], ls3); atomicAdd(&s_sq[c + 3], lq3);
    __syncthreads();
    if (tid < HID_DIM) {
        atomicAdd(&g_bnsum[tid], s_sum[tid]);
        atomicAdd(&g_bnsq [tid], s_sq [tid]);
    }
}

// ---------------------------------------------------------------------------
// 10. BN finalize: A = gamma*rsqrt(var+eps), B = beta - mean*A
// ---------------------------------------------------------------------------
__global__ void bn_finalize_kernel(const float* __restrict__ gamma,
                                   const float* __restrict__ beta,
                                   double invN) {
    int c = threadIdx.x;      // 128 threads
    double mean = g_bnsum[c] * invN;
    double var  = g_bnsq[c] * invN - mean * mean;
    float A = gamma[c] * rsqrtf((float)var + BN_EPS);
    g_A[c] = A;
    g_B[c] = beta[c] - (float)mean * A;
}

// ---------------------------------------------------------------------------
// 11. GEMM2: t2 = (relu(y1*A+B) * rs_out[:,None]) @ W2   [N,128]@[128,64]
//     BN + ReLU + degree-scale fused into the smem tile loader.
// ---------------------------------------------------------------------------
__global__ void gemm2_kernel(const float* __restrict__ W, int N) {
    extern __shared__ float smem[];
    float* Ws = smem;                 // 128*64
    float* Xs = smem + 128 * 64;      // 64*128
    int tid = threadIdx.x;

    const float4* W4 = (const float4*)W;
    float4* Ws4 = (float4*)Ws;
    #pragma unroll 4
    for (int i = tid; i < 128 * 64 / 4; i += 256) Ws4[i] = W4[i];

    int row0 = blockIdx.x * 64;
    float4* Xs4 = (float4*)Xs;
    for (int i = tid; i < 64 * 32; i += 256) {
        int r = i >> 5, c = i & 31;
        int row = row0 + r;
        float4 x = make_float4(0.f, 0.f, 0.f, 0.f);
        if (row < N) {
            float4 y  = ((const float4*)g_y1)[(size_t)row * 32 + c];
            float4 Av = ((const float4*)g_A)[c];
            float4 Bv = ((const float4*)g_B)[c];
            float s = g_rs_out[row];
            x.x = fmaxf(fmaf(y.x, Av.x, Bv.x), 0.f) * s;
            x.y = fmaxf(fmaf(y.y, Av.y, Bv.y), 0.f) * s;
            x.z = fmaxf(fmaf(y.z, Av.z, Bv.z), 0.f) * s;
            x.w = fmaxf(fmaf(y.w, Av.w, Bv.w), 0.f) * s;
        }
        Xs4[i] = x;
    }
    __syncthreads();

    int lane  = tid & 31;
    int rbase = (tid >> 5) * 8;
    float acc[8][2];
    #pragma unroll
    for (int r = 0; r < 8; r++) acc[r][0] = acc[r][1] = 0.f;

    for (int k = 0; k < 128; k += 4) {
        float4 xv[8];
        #pragma unroll
        for (int r = 0; r < 8; r++)
            xv[r] = *(const float4*)&Xs[(rbase + r) * 128 + k];
        #pragma unroll
        for (int kk = 0; kk < 4; kk++) {
            float2 wv = *(const float2*)&Ws[(k + kk) * 64 + lane * 2];
            #pragma unroll
            for (int r = 0; r < 8; r++) {
                float x = (kk == 0) ? xv[r].x : (kk == 1) ? xv[r].y
                        : (kk == 2) ? xv[r].z : xv[r].w;
                acc[r][0] = fmaf(x, wv.x, acc[r][0]);
                acc[r][1] = fmaf(x, wv.y, acc[r][1]);
            }
        }
    }
    #pragma unroll
    for (int r = 0; r < 8; r++) {
        int row = row0 + rbase + r;
        if (row < N)
            ((float2*)g_t2)[(size_t)row * 32 + lane] =
                make_float2(acc[r][0], acc[r][1]);
    }
}

// ---------------------------------------------------------------------------
// 12. SpMM2: out[i] = (sum t2[csr[e]]) * rs_in[i] + b2  (64-wide, float2/lane)
//     4 independent chains per lane (MLP=4).
// ---------------------------------------------------------------------------
__global__ void spmm2_kernel(const float* __restrict__ b2,
                             float* __restrict__ out, int N) {
    int tid = threadIdx.x;
    int lane = tid & 31;
    int gw = (blockIdx.x * blockDim.x + tid) >> 5;
    int nw = (gridDim.x * blockDim.x) >> 5;

    const float2* __restrict__ t22 = (const float2*)g_t2;
    float2 bb = ((const float2*)b2)[lane];

    for (int i = gw; i < N; i += nw) {
        int beg = g_rowp[i], end = g_rowp[i + 1];
        float2 a0 = make_float2(0.f, 0.f);
        float2 a1 = make_float2(0.f, 0.f);
        float2 a2 = make_float2(0.f, 0.f);
        float2 a3 = make_float2(0.f, 0.f);
        int e = beg;
        for (; e + 3 < end; e += 4) {
            int s0 = g_csr[e], s1 = g_csr[e + 1];
            int s2 = g_csr[e + 2], s3 = g_csr[e + 3];
            float2 v0 = t22[(size_t)s0 * 32 + lane];
            float2 v1 = t22[(size_t)s1 * 32 + lane];
            float2 v2 = t22[(size_t)s2 * 32 + lane];
            float2 v3 = t22[(size_t)s3 * 32 + lane];
            a0.x += v0.x; a0.y += v0.y;
            a1.x += v1.x; a1.y += v1.y;
            a2.x += v2.x; a2.y += v2.y;
            a3.x += v3.x; a3.y += v3.y;
        }
        for (; e < end; e++) {
            int s0 = g_csr[e];
            float2 v0 = t22[(size_t)s0 * 32 + lane];
            a0.x += v0.x; a0.y += v0.y;
        }
        float r = g_rs_in[i];
        float2 y;
        y.x = ((a0.x + a1.x) + (a2.x + a3.x)) * r + bb.x;
        y.y = ((a0.y + a1.y) + (a2.y + a3.y)) * r + bb.y;
        ((float2*)out)[(size_t)i * 32 + lane] = y;
    }
}

// ---------------------------------------------------------------------------
// Host launcher
// ---------------------------------------------------------------------------
extern "C" void kernel_launch(void* const* d_in, const int* in_sizes, int n_in,
                              void* d_out, int out_size) {
    const float* h     = (const float*)d_in[0];
    const float* W1    = (const float*)d_in[1];
    const float* b1    = (const float*)d_in[2];
    const float* W2    = (const float*)d_in[3];
    const float* b2    = (const float*)d_in[4];
    const float* gamma = (const float*)d_in[5];
    const float* beta  = (const float*)d_in[6];
    const int*   src   = (const int*)d_in[7];
    const int*   dst   = (const int*)d_in[8];

    int N = in_sizes[0] / IN_DIM;
    int E = in_sizes[7];
    if (N > MAXN || E > MAXE) return;  // shape is fixed; safety only

    // Opt-in dynamic smem (idempotent every call; not a stream op)
    cudaFuncSetAttribute(gemm1_kernel,
        cudaFuncAttributeMaxDynamicSharedMemorySize, (128*128 + 64*128) * 4);
    cudaFuncSetAttribute(gemm2_kernel,
        cudaFuncAttributeMaxDynamicSharedMemorySize, (128*64 + 64*128) * 4);

    int tb = 256;
    int nBlkN = (N + tb - 1) / tb;
    int nBlkE = (E + tb - 1) / tb;
    int nb = (N + 1023) / 1024;

    zero_kernel     <<<nBlkN, tb>>>(N);
    hist_kernel     <<<nBlkE, tb>>>(src, dst, E);
    rsqrt_kernel    <<<nBlkN, tb>>>(N);
    scan_a_kernel   <<<nb, 1024>>>(N);
    scan_b_kernel   <<<1, 1024>>>(nb);
    scan_c_kernel   <<<nb, 1024>>>(N, E);
    csr_fill_kernel <<<nBlkE, tb>>>(src, dst, E);

    gemm1_kernel<<<(N + 63) / 64, 256, (128*128 + 64*128) * 4>>>(h, W1, N);
    spmm1_kernel<<<1184, 256>>>(b1, N);
    bn_finalize_kernel<<<1, HID_DIM>>>(gamma, beta, 1.0 / (double)N);
    gemm2_kernel<<<(N + 63) / 64, 256, (128*64 + 64*128) * 4>>>(W2, N);
    spmm2_kernel<<<1184, 256>>>(b2, (float*)d_out, N);
}

// round 5
// speedup vs baseline: 1.1153x; 1.1153x over previous
#include <cuda_runtime.h>
#include <cuda_bf16.h>
#include <math.h>

// ---------------------------------------------------------------------------
// Problem constants (fixed by the dataset; runtime values checked to fit)
// ---------------------------------------------------------------------------
#define MAXN 100352          // >= N=100000, multiple of 1024 and 64
#define MAXE 1600000         // == E
#define IN_DIM 128
#define HID_DIM 128
#define OUT_DIM 64
#define BN_EPS 1e-5f

// ---------------------------------------------------------------------------
// Scratch (device globals; no runtime allocation allowed)
// ---------------------------------------------------------------------------
__device__ int    g_cnt_in [MAXN];
__device__ int    g_cnt_out[MAXN];
__device__ float  g_rs_in  [MAXN];
__device__ float  g_rs_out [MAXN];
__device__ int    g_rowp   [MAXN + 1];
__device__ int    g_cursor [MAXN];
__device__ int    g_csr    [MAXE];
__device__ int    g_bsum   [1024];

__device__ float  g_t1[(size_t)MAXN * HID_DIM];  // (h*rs_out)@W1
__device__ float  g_y1[(size_t)MAXN * HID_DIM];  // post-aggregation layer1 out
__device__ float  g_t2[(size_t)MAXN * OUT_DIM];  // (bnrelu(y1)*rs_out)@W2

__device__ double g_bnsum[HID_DIM];
__device__ double g_bnsq [HID_DIM];
__device__ float  g_A[HID_DIM];   // gamma * rsqrt(var+eps)
__device__ float  g_B[HID_DIM];   // beta - mean * A

// ---------------------------------------------------------------------------
// 1. Zero counters + BN accumulators
// ---------------------------------------------------------------------------
__global__ void zero_kernel(int N) {
    int i = blockIdx.x * blockDim.x + threadIdx.x;
    if (i < N) { g_cnt_in[i] = 0; g_cnt_out[i] = 0; }
    if (i < HID_DIM) { g_bnsum[i] = 0.0; g_bnsq[i] = 0.0; }
}

// ---------------------------------------------------------------------------
// 2. Degree histograms
// ---------------------------------------------------------------------------
__global__ void hist_kernel(const int* __restrict__ src,
                            const int* __restrict__ dst, int E) {
    int e = blockIdx.x * blockDim.x + threadIdx.x;
    if (e < E) {
        atomicAdd(&g_cnt_out[src[e]], 1);
        atomicAdd(&g_cnt_in [dst[e]], 1);
    }
}

// ---------------------------------------------------------------------------
// 3-5. Exclusive scan of in-degrees -> row_ptr (3-phase block scan).
//      Phase C also computes rsqrt degree scalings (fused; saves a kernel).
// ---------------------------------------------------------------------------
__global__ void scan_a_kernel(int N) {
    __shared__ int sh[1024];
    int tid = threadIdx.x;
    int i = blockIdx.x * 1024 + tid;
    int v = (i < N) ? g_cnt_in[i] : 0;
    sh[tid] = v;
    __syncthreads();
    for (int off = 1; off < 1024; off <<= 1) {
        int t = 0;
        if (tid >= off) t = sh[tid - off];
        __syncthreads();
        sh[tid] += t;
        __syncthreads();
    }
    if (i < N) g_rowp[i] = sh[tid] - v;     // exclusive within block
    if (tid == 1023) g_bsum[blockIdx.x] = sh[tid];
}

__global__ void scan_b_kernel(int nb) {
    __shared__ int sh[1024];
    int tid = threadIdx.x;
    int v = (tid < nb) ? g_bsum[tid] : 0;
    sh[tid] = v;
    __syncthreads();
    for (int off = 1; off < 1024; off <<= 1) {
        int t = 0;
        if (tid >= off) t = sh[tid - off];
        __syncthreads();
        sh[tid] += t;
        __syncthreads();
    }
    if (tid < nb) g_bsum[tid] = sh[tid] - v; // exclusive block offsets
}

__global__ void scan_c_kernel(int N, int E) {
    int i = blockIdx.x * 1024 + threadIdx.x;
    if (i < N) {
        int v = g_rowp[i] + g_bsum[blockIdx.x];
        g_rowp[i] = v;
        g_cursor[i] = v;
        int ci = g_cnt_in[i];  if (ci < 1) ci = 1;
        int co = g_cnt_out[i]; if (co < 1) co = 1;
        g_rs_in[i]  = rsqrtf((float)ci);
        g_rs_out[i] = rsqrtf((float)co);
    }
    if (i == 0) g_rowp[N] = E;
}

// ---------------------------------------------------------------------------
// 6. CSR fill (dst-bucketed list of src indices)
// ---------------------------------------------------------------------------
__global__ void csr_fill_kernel(const int* __restrict__ src,
                                const int* __restrict__ dst, int E) {
    int e = blockIdx.x * blockDim.x + threadIdx.x;
    if (e < E) {
        int d = dst[e];
        int p = atomicAdd(&g_cursor[d], 1);
        g_csr[p] = src[e];
    }
}

// ---------------------------------------------------------------------------
// 7. GEMM1: t1 = (h * rs_out[:,None]) @ W1     [N,128]@[128,128]
//    256 threads, 64 rows/block. W1 + scaled X tile in dyn smem.
//    Each thread: 8 rows x 4 cols (warp rows uniform -> broadcast LDS).
// ---------------------------------------------------------------------------
__global__ void gemm1_kernel(const float* __restrict__ h,
                             const float* __restrict__ W, int N) {
    extern __shared__ float smem[];
    float* Ws = smem;                 // 128*128
    float* Xs = smem + 128 * 128;     // 64*128
    int tid = threadIdx.x;

    const float4* W4 = (const float4*)W;
    float4* Ws4 = (float4*)Ws;
    #pragma unroll 4
    for (int i = tid; i < 128 * 128 / 4; i += 256) Ws4[i] = W4[i];

    int row0 = blockIdx.x * 64;
    float4* Xs4 = (float4*)Xs;
    for (int i = tid; i < 64 * 32; i += 256) {
        int r = i >> 5, c = i & 31;
        int row = row0 + r;
        float4 v = make_float4(0.f, 0.f, 0.f, 0.f);
        if (row < N) {
            v = ((const float4*)h)[(size_t)row * 32 + c];
            float s = g_rs_out[row];
            v.x *= s; v.y *= s; v.z *= s; v.w *= s;
        }
        Xs4[i] = v;
    }
    __syncthreads();

    int lane  = tid & 31;
    int rbase = (tid >> 5) * 8;
    float acc[8][4];
    #pragma unroll
    for (int r = 0; r < 8; r++)
        acc[r][0] = acc[r][1] = acc[r][2] = acc[r][3] = 0.f;

    for (int k = 0; k < 128; k += 4) {
        float4 xv[8];
        #pragma unroll
        for (int r = 0; r < 8; r++)
            xv[r] = *(const float4*)&Xs[(rbase + r) * 128 + k];
        #pragma unroll
        for (int kk = 0; kk < 4; kk++) {
            float4 wv = *(const float4*)&Ws[(k + kk) * 128 + lane * 4];
            #pragma unroll
            for (int r = 0; r < 8; r++) {
                float x = (kk == 0) ? xv[r].x : (kk == 1) ? xv[r].y
                        : (kk == 2) ? xv[r].z : xv[r].w;
                acc[r][0] = fmaf(x, wv.x, acc[r][0]);
                acc[r][1] = fmaf(x, wv.y, acc[r][1]);
                acc[r][2] = fmaf(x, wv.z, acc[r][2]);
                acc[r][3] = fmaf(x, wv.w, acc[r][3]);
            }
        }
    }
    #pragma unroll
    for (int r = 0; r < 8; r++) {
        int row = row0 + rbase + r;
        if (row < N)
            ((float4*)g_t1)[(size_t)row * 32 + lane] =
                make_float4(acc[r][0], acc[r][1], acc[r][2], acc[r][3]);
    }
}

// ---------------------------------------------------------------------------
// 8. SpMM1: y1[i] = (sum_{e in row i} t1[csr[e]]) * rs_in[i] + b1
//    Warp-per-node, lane covers 4 contiguous cols (float4).
//    8 gathers batched per inner iteration (MLP_p1 ~ 8) -> cover L2 latency.
//    Fused BN statistics: fp32 per-thread -> double smem -> double global.
// ---------------------------------------------------------------------------
__global__ void __launch_bounds__(256, 4)
spmm1_kernel(const float* __restrict__ b1, int N) {
    __shared__ double s_sum[HID_DIM];
    __shared__ double s_sq [HID_DIM];
    int tid = threadIdx.x;
    if (tid < HID_DIM) { s_sum[tid] = 0.0; s_sq[tid] = 0.0; }
    __syncthreads();

    int lane = tid & 31;
    int gw = (blockIdx.x * blockDim.x + tid) >> 5;
    int nw = (gridDim.x * blockDim.x) >> 5;

    const float4* __restrict__ t14 = (const float4*)g_t1;
    const int*    __restrict__ csr = g_csr;
    float4 bb = ((const float4*)b1)[lane];

    float ls0 = 0.f, ls1 = 0.f, ls2 = 0.f, ls3 = 0.f;
    float lq0 = 0.f, lq1 = 0.f, lq2 = 0.f, lq3 = 0.f;

    for (int i = gw; i < N; i += nw) {
        int beg = g_rowp[i], end = g_rowp[i + 1];
        float4 a = make_float4(0.f, 0.f, 0.f, 0.f);
        int e = beg;
        // 8-deep batches: loads issue back-to-back, then one fold
        for (; e + 8 <= end; e += 8) {
            float4 v[8];
            #pragma unroll
            for (int j = 0; j < 8; j++) {
                int s = csr[e + j];
                v[j] = t14[(size_t)s * 32 + lane];
            }
            #pragma unroll
            for (int j = 0; j < 8; j++) {
                a.x += v[j].x; a.y += v[j].y; a.z += v[j].z; a.w += v[j].w;
            }
        }
        if (e + 4 <= end) {
            float4 v[4];
            #pragma unroll
            for (int j = 0; j < 4; j++) {
                int s = csr[e + j];
                v[j] = t14[(size_t)s * 32 + lane];
            }
            #pragma unroll
            for (int j = 0; j < 4; j++) {
                a.x += v[j].x; a.y += v[j].y; a.z += v[j].z; a.w += v[j].w;
            }
            e += 4;
        }
        if (e + 2 <= end) {
            int s0 = csr[e], s1 = csr[e + 1];
            float4 v0 = t14[(size_t)s0 * 32 + lane];
            float4 v1 = t14[(size_t)s1 * 32 + lane];
            a.x += v0.x + v1.x; a.y += v0.y + v1.y;
            a.z += v0.z + v1.z; a.w += v0.w + v1.w;
            e += 2;
        }
        if (e < end) {
            int s0 = csr[e];
            float4 v0 = t14[(size_t)s0 * 32 + lane];
            a.x += v0.x; a.y += v0.y; a.z += v0.z; a.w += v0.w;
        }
        float r = g_rs_in[i];
        float4 y;
        y.x = a.x * r + bb.x;
        y.y = a.y * r + bb.y;
        y.z = a.z * r + bb.z;
        y.w = a.w * r + bb.w;
        ((float4*)g_y1)[(size_t)i * 32 + lane] = y;

        ls0 += y.x; lq0 += y.x * y.x;
        ls1 += y.y; lq1 += y.y * y.y;
        ls2 += y.z; lq2 += y.z * y.z;
        ls3 += y.w; lq3 += y.w * y.w;
    }
    int c = lane * 4;
    atomicAdd(&s_sum[c + 0], (double)ls0); atomicAdd(&s_sq[c + 0], (double)lq0);
    atomicAdd(&s_sum[c + 1], (double)ls1); atomicAdd(&s_sq[c + 1], (double)lq1);
    atomicAdd(&s_sum[c + 2], (double)ls2); atomicAdd(&s_sq[c + 2], (double)lq2);
    atomicAdd(&s_sum[c + 3], (double)ls3); atomicAdd(&s_sq[c + 3], (double)lq3);
    __syncthreads();
    if (tid < HID_DIM) {
        atomicAdd(&g_bnsum[tid], s_sum[tid]);
        atomicAdd(&g_bnsq [tid], s_sq [tid]);
    }
}

// ---------------------------------------------------------------------------
// 9. BN finalize: A = gamma*rsqrt(var+eps), B = beta - mean*A
// ---------------------------------------------------------------------------
__global__ void bn_finalize_kernel(const float* __restrict__ gamma,
                                   const float* __restrict__ beta,
                                   double invN) {
    int c = threadIdx.x;      // 128 threads
    double mean = g_bnsum[c] * invN;
    double var  = g_bnsq[c] * invN - mean * mean;
    float A = gamma[c] * rsqrtf((float)var + BN_EPS);
    g_A[c] = A;
    g_B[c] = beta[c] - (float)mean * A;
}

// ---------------------------------------------------------------------------
// 10. GEMM2: t2 = (relu(y1*A+B) * rs_out[:,None]) @ W2   [N,128]@[128,64]
//     BN + ReLU + degree-scale fused into the smem tile loader.
// ---------------------------------------------------------------------------
__global__ void gemm2_kernel(const float* __restrict__ W, int N) {
    extern __shared__ float smem[];
    float* Ws = smem;                 // 128*64
    float* Xs = smem + 128 * 64;      // 64*128
    int tid = threadIdx.x;

    const float4* W4 = (const float4*)W;
    float4* Ws4 = (float4*)Ws;
    #pragma unroll 4
    for (int i = tid; i < 128 * 64 / 4; i += 256) Ws4[i] = W4[i];

    int row0 = blockIdx.x * 64;
    float4* Xs4 = (float4*)Xs;
    for (int i = tid; i < 64 * 32; i += 256) {
        int r = i >> 5, c = i & 31;
        int row = row0 + r;
        float4 x = make_float4(0.f, 0.f, 0.f, 0.f);
        if (row < N) {
            float4 y  = ((const float4*)g_y1)[(size_t)row * 32 + c];
            float4 Av = ((const float4*)g_A)[c];
            float4 Bv = ((const float4*)g_B)[c];
            float s = g_rs_out[row];
            x.x = fmaxf(fmaf(y.x, Av.x, Bv.x), 0.f) * s;
            x.y = fmaxf(fmaf(y.y, Av.y, Bv.y), 0.f) * s;
            x.z = fmaxf(fmaf(y.z, Av.z, Bv.z), 0.f) * s;
            x.w = fmaxf(fmaf(y.w, Av.w, Bv.w), 0.f) * s;
        }
        Xs4[i] = x;
    }
    __syncthreads();

    int lane  = tid & 31;
    int rbase = (tid >> 5) * 8;
    float acc[8][2];
    #pragma unroll
    for (int r = 0; r < 8; r++) acc[r][0] = acc[r][1] = 0.f;

    for (int k = 0; k < 128; k += 4) {
        float4 xv[8];
        #pragma unroll
        for (int r = 0; r < 8; r++)
            xv[r] = *(const float4*)&Xs[(rbase + r) * 128 + k];
        #pragma unroll
        for (int kk = 0; kk < 4; kk++) {
            float2 wv = *(const float2*)&Ws[(k + kk) * 64 + lane * 2];
            #pragma unroll
            for (int r = 0; r < 8; r++) {
                float x = (kk == 0) ? xv[r].x : (kk == 1) ? xv[r].y
                        : (kk == 2) ? xv[r].z : xv[r].w;
                acc[r][0] = fmaf(x, wv.x, acc[r][0]);
                acc[r][1] = fmaf(x, wv.y, acc[r][1]);
            }
        }
    }
    #pragma unroll
    for (int r = 0; r < 8; r++) {
        int row = row0 + rbase + r;
        if (row < N)
            ((float2*)g_t2)[(size_t)row * 32 + lane] =
                make_float2(acc[r][0], acc[r][1]);
    }
}

// ---------------------------------------------------------------------------
// 11. SpMM2: out[i] = (sum t2[csr[e]]) * rs_in[i] + b2  (64-wide, float2/lane)
//     8-deep load batching (MLP_p1 ~ 8).
// ---------------------------------------------------------------------------
__global__ void __launch_bounds__(256, 4)
spmm2_kernel(const float* __restrict__ b2,
             float* __restrict__ out, int N) {
    int tid = threadIdx.x;
    int lane = tid & 31;
    int gw = (blockIdx.x * blockDim.x + tid) >> 5;
    int nw = (gridDim.x * blockDim.x) >> 5;

    const float2* __restrict__ t22 = (const float2*)g_t2;
    const int*    __restrict__ csr = g_csr;
    float2 bb = ((const float2*)b2)[lane];

    for (int i = gw; i < N; i += nw) {
        int beg = g_rowp[i], end = g_rowp[i + 1];
        float2 a = make_float2(0.f, 0.f);
        int e = beg;
        for (; e + 8 <= end; e += 8) {
            float2 v[8];
            #pragma unroll
            for (int j = 0; j < 8; j++) {
                int s = csr[e + j];
                v[j] = t22[(size_t)s * 32 + lane];
            }
            #pragma unroll
            for (int j = 0; j < 8; j++) { a.x += v[j].x; a.y += v[j].y; }
        }
        if (e + 4 <= end) {
            float2 v[4];
            #pragma unroll
            for (int j = 0; j < 4; j++) {
                int s = csr[e + j];
                v[j] = t22[(size_t)s * 32 + lane];
            }
            #pragma unroll
            for (int j = 0; j < 4; j++) { a.x += v[j].x; a.y += v[j].y; }
            e += 4;
        }
        if (e + 2 <= end) {
            int s0 = csr[e], s1 = csr[e + 1];
            float2 v0 = t22[(size_t)s0 * 32 + lane];
            float2 v1 = t22[(size_t)s1 * 32 + lane];
            a.x += v0.x + v1.x; a.y += v0.y + v1.y;
            e += 2;
        }
        if (e < end) {
            int s0 = csr[e];
            float2 v0 = t22[(size_t)s0 * 32 + lane];
            a.x += v0.x; a.y += v0.y;
        }
        float r = g_rs_in[i];
        float2 y;
        y.x = a.x * r + bb.x;
        y.y = a.y * r + bb.y;
        ((float2*)out)[(size_t)i * 32 + lane] = y;
    }
}

// ---------------------------------------------------------------------------
// Host launcher
// ---------------------------------------------------------------------------
extern "C" void kernel_launch(void* const* d_in, const int* in_sizes, int n_in,
                              void* d_out, int out_size) {
    const float* h     = (const float*)d_in[0];
    const float* W1    = (const float*)d_in[1];
    const float* b1    = (const float*)d_in[2];
    const float* W2    = (const float*)d_in[3];
    const float* b2    = (const float*)d_in[4];
    const float* gamma = (const float*)d_in[5];
    const float* beta  = (const float*)d_in[6];
    const int*   src   = (const int*)d_in[7];
    const int*   dst   = (const int*)d_in[8];

    int N = in_sizes[0] / IN_DIM;
    int E = in_sizes[7];
    if (N > MAXN || E > MAXE) return;  // shape is fixed; safety only

    // Opt-in dynamic smem (idempotent every call; not a stream op)
    cudaFuncSetAttribute(gemm1_kernel,
        cudaFuncAttributeMaxDynamicSharedMemorySize, (128*128 + 64*128) * 4);
    cudaFuncSetAttribute(gemm2_kernel,
        cudaFuncAttributeMaxDynamicSharedMemorySize, (128*64 + 64*128) * 4);

    int tb = 256;
    int nBlkN = (N + tb - 1) / tb;
    int nBlkE = (E + tb - 1) / tb;
    int nb = (N + 1023) / 1024;

    zero_kernel     <<<nBlkN, tb>>>(N);
    hist_kernel     <<<nBlkE, tb>>>(src, dst, E);
    scan_a_kernel   <<<nb, 1024>>>(N);
    scan_b_kernel   <<<1, 1024>>>(nb);
    scan_c_kernel   <<<nb, 1024>>>(N, E);
    csr_fill_kernel <<<nBlkE, tb>>>(src, dst, E);

    gemm1_kernel<<<(N + 63) / 64, 256, (128*128 + 64*128) * 4>>>(h, W1, N);
    spmm1_kernel<<<592, 256>>>(b1, N);
    bn_finalize_kernel<<<1, HID_DIM>>>(gamma, beta, 1.0 / (double)N);
    gemm2_kernel<<<(N + 63) / 64, 256, (128*64 + 64*128) * 4>>>(W2, N);
    spmm2_kernel<<<592, 256>>>(b2, (float*)d_out, N);
}

// round 9
// speedup vs baseline: 1.1566x; 1.0371x over previous
#include <cuda_runtime.h>
#include <cuda_bf16.h>
#include <cuda_fp16.h>
#include <math.h>

// ---------------------------------------------------------------------------
// Problem constants (fixed by the dataset; runtime values checked to fit)
// ---------------------------------------------------------------------------
#define MAXN 100352          // >= N=100000, multiple of 1024 and 64
#define MAXE 1600000         // == E
#define IN_DIM 128
#define HID_DIM 128
#define OUT_DIM 64
#define BN_EPS 1e-5f

// ---------------------------------------------------------------------------
// Scratch (device globals; no runtime allocation allowed)
// ---------------------------------------------------------------------------
__device__ int    g_cnt_in [MAXN];
__device__ int    g_cnt_out[MAXN];
__device__ float  g_rs_in  [MAXN];
__device__ float  g_rs_out [MAXN];
__device__ int    g_rowp   [MAXN + 1];
__device__ int    g_cursor [MAXN];
__device__ int    g_csr    [MAXE];
__device__ int    g_bsum   [1024];

__device__ __half g_t1h[(size_t)MAXN * HID_DIM];  // fp16 (h*rs_out)@W1
__device__ float  g_y1 [(size_t)MAXN * HID_DIM];  // fp32 layer1 output
__device__ __half g_t2h[(size_t)MAXN * OUT_DIM];  // fp16 (bnrelu(y1)*rs_out)@W2

__device__ double g_bnsum[HID_DIM];
__device__ double g_bnsq [HID_DIM];
__device__ float  g_A[HID_DIM];   // gamma * rsqrt(var+eps)
__device__ float  g_B[HID_DIM];   // beta - mean * A

// ---------------------------------------------------------------------------
// 1. Zero counters + BN accumulators
// ---------------------------------------------------------------------------
__global__ void zero_kernel(int N) {
    int i = blockIdx.x * blockDim.x + threadIdx.x;
    if (i < N) { g_cnt_in[i] = 0; g_cnt_out[i] = 0; }
    if (i < HID_DIM) { g_bnsum[i] = 0.0; g_bnsq[i] = 0.0; }
}

// ---------------------------------------------------------------------------
// 2. Degree histograms
// ---------------------------------------------------------------------------
__global__ void hist_kernel(const int* __restrict__ src,
                            const int* __restrict__ dst, int E) {
    int e = blockIdx.x * blockDim.x + threadIdx.x;
    if (e < E) {
        atomicAdd(&g_cnt_out[src[e]], 1);
        atomicAdd(&g_cnt_in [dst[e]], 1);
    }
}

// ---------------------------------------------------------------------------
// 3-5. Exclusive scan of in-degrees -> row_ptr (3-phase block scan).
//      Phase C also computes rsqrt degree scalings (fused).
// ---------------------------------------------------------------------------
__global__ void scan_a_kernel(int N) {
    __shared__ int sh[1024];
    int tid = threadIdx.x;
    int i = blockIdx.x * 1024 + tid;
    int v = (i < N) ? g_cnt_in[i] : 0;
    sh[tid] = v;
    __syncthreads();
    for (int off = 1; off < 1024; off <<= 1) {
        int t = 0;
        if (tid >= off) t = sh[tid - off];
        __syncthreads();
        sh[tid] += t;
        __syncthreads();
    }
    if (i < N) g_rowp[i] = sh[tid] - v;     // exclusive within block
    if (tid == 1023) g_bsum[blockIdx.x] = sh[tid];
}

__global__ void scan_b_kernel(int nb) {
    __shared__ int sh[1024];
    int tid = threadIdx.x;
    int v = (tid < nb) ? g_bsum[tid] : 0;
    sh[tid] = v;
    __syncthreads();
    for (int off = 1; off < 1024; off <<= 1) {
        int t = 0;
        if (tid >= off) t = sh[tid - off];
        __syncthreads();
        sh[tid] += t;
        __syncthreads();
    }
    if (tid < nb) g_bsum[tid] = sh[tid] - v; // exclusive block offsets
}

__global__ void scan_c_kernel(int N, int E) {
    int i = blockIdx.x * 1024 + threadIdx.x;
    if (i < N) {
        int v = g_rowp[i] + g_bsum[blockIdx.x];
        g_rowp[i] = v;
        g_cursor[i] = v;
        int ci = g_cnt_in[i];  if (ci < 1) ci = 1;
        int co = g_cnt_out[i]; if (co < 1) co = 1;
        g_rs_in[i]  = rsqrtf((float)ci);
        g_rs_out[i] = rsqrtf((float)co);
    }
    if (i == 0) g_rowp[N] = E;
}

// ---------------------------------------------------------------------------
// 6. CSR fill (dst-bucketed list of src indices)
// ---------------------------------------------------------------------------
__global__ void csr_fill_kernel(const int* __restrict__ src,
                                const int* __restrict__ dst, int E) {
    int e = blockIdx.x * blockDim.x + threadIdx.x;
    if (e < E) {
        int d = dst[e];
        int p = atomicAdd(&g_cursor[d], 1);
        g_csr[p] = src[e];
    }
}

// ---------------------------------------------------------------------------
// 7. GEMM1: t1h = fp16( (h * rs_out[:,None]) @ W1 )    [N,128]@[128,128]
//    256 threads, 64 rows/block. W1 + scaled X tile in dyn smem.
//    Each thread: 8 rows x 4 cols. Epilogue converts to fp16.
// ---------------------------------------------------------------------------
__global__ void gemm1_kernel(const float* __restrict__ h,
                             const float* __restrict__ W, int N) {
    extern __shared__ float smem[];
    float* Ws = smem;                 // 128*128
    float* Xs = smem + 128 * 128;     // 64*128
    int tid = threadIdx.x;

    const float4* W4 = (const float4*)W;
    float4* Ws4 = (float4*)Ws;
    #pragma unroll 4
    for (int i = tid; i < 128 * 128 / 4; i += 256) Ws4[i] = W4[i];

    int row0 = blockIdx.x * 64;
    float4* Xs4 = (float4*)Xs;
    for (int i = tid; i < 64 * 32; i += 256) {
        int r = i >> 5, c = i & 31;
        int row = row0 + r;
        float4 v = make_float4(0.f, 0.f, 0.f, 0.f);
        if (row < N) {
            v = ((const float4*)h)[(size_t)row * 32 + c];
            float s = g_rs_out[row];
            v.x *= s; v.y *= s; v.z *= s; v.w *= s;
        }
        Xs4[i] = v;
    }
    __syncthreads();

    int lane  = tid & 31;
    int rbase = (tid >> 5) * 8;
    float acc[8][4];
    #pragma unroll
    for (int r = 0; r < 8; r++)
        acc[r][0] = acc[r][1] = acc[r][2] = acc[r][3] = 0.f;

    for (int k = 0; k < 128; k += 4) {
        float4 xv[8];
        #pragma unroll
        for (int r = 0; r < 8; r++)
            xv[r] = *(const float4*)&Xs[(rbase + r) * 128 + k];
        #pragma unroll
        for (int kk = 0; kk < 4; kk++) {
            float4 wv = *(const float4*)&Ws[(k + kk) * 128 + lane * 4];
            #pragma unroll
            for (int r = 0; r < 8; r++) {
                float x = (kk == 0) ? xv[r].x : (kk == 1) ? xv[r].y
                        : (kk == 2) ? xv[r].z : xv[r].w;
                acc[r][0] = fmaf(x, wv.x, acc[r][0]);
                acc[r][1] = fmaf(x, wv.y, acc[r][1]);
                acc[r][2] = fmaf(x, wv.z, acc[r][2]);
                acc[r][3] = fmaf(x, wv.w, acc[r][3]);
            }
        }
    }
    #pragma unroll
    for (int r = 0; r < 8; r++) {
        int row = row0 + rbase + r;
        if (row < N) {
            __half2 p0 = __floats2half2_rn(acc[r][0], acc[r][1]);
            __half2 p1 = __floats2half2_rn(acc[r][2], acc[r][3]);
            uint2 u;
            u.x = *(unsigned int*)&p0;
            u.y = *(unsigned int*)&p1;
            ((uint2*)g_t1h)[(size_t)row * 32 + lane] = u;
        }
    }
}

// ---------------------------------------------------------------------------
// 8. SpMM1: y1[i] = (sum_{e in row i} t1h[csr[e]]) * rs_in[i] + b1
//    Warp-per-node, lane covers 4 contiguous cols (fp16x4 = uint2, 8B).
//    8 gathers batched per inner iteration; fp32 accumulation.
//    Fused BN statistics: fp32 per-thread -> double smem -> double global.
// ---------------------------------------------------------------------------
__global__ void __launch_bounds__(256, 4)
spmm1_kernel(const float* __restrict__ b1, int N) {
    __shared__ double s_sum[HID_DIM];
    __shared__ double s_sq [HID_DIM];
    int tid = threadIdx.x;
    if (tid < HID_DIM) { s_sum[tid] = 0.0; s_sq[tid] = 0.0; }
    __syncthreads();

    int lane = tid & 31;
    int gw = (blockIdx.x * blockDim.x + tid) >> 5;
    int nw = (gridDim.x * blockDim.x) >> 5;

    const uint2* __restrict__ t1h = (const uint2*)g_t1h;
    const int*   __restrict__ csr = g_csr;
    float4 bb = ((const float4*)b1)[lane];

    float ls0 = 0.f, ls1 = 0.f, ls2 = 0.f, ls3 = 0.f;
    float lq0 = 0.f, lq1 = 0.f, lq2 = 0.f, lq3 = 0.f;

    for (int i = gw; i < N; i += nw) {
        int beg = g_rowp[i], end = g_rowp[i + 1];
        float4 a = make_float4(0.f, 0.f, 0.f, 0.f);
        int e = beg;
        // 8-deep batches: loads issue back-to-back, then one fold
        for (; e + 8 <= end; e += 8) {
            uint2 v[8];
            #pragma unroll
            for (int j = 0; j < 8; j++) {
                int s = csr[e + j];
                v[j] = t1h[(size_t)s * 32 + lane];
            }
            #pragma unroll
            for (int j = 0; j < 8; j++) {
                float2 f0 = __half22float2(*(__half2*)&v[j].x);
                float2 f1 = __half22float2(*(__half2*)&v[j].y);
                a.x += f0.x; a.y += f0.y; a.z += f1.x; a.w += f1.y;
            }
        }
        if (e + 4 <= end) {
            uint2 v[4];
            #pragma unroll
            for (int j = 0; j < 4; j++) {
                int s = csr[e + j];
                v[j] = t1h[(size_t)s * 32 + lane];
            }
            #pragma unroll
            for (int j = 0; j < 4; j++) {
                float2 f0 = __half22float2(*(__half2*)&v[j].x);
                float2 f1 = __half22float2(*(__half2*)&v[j].y);
                a.x += f0.x; a.y += f0.y; a.z += f1.x; a.w += f1.y;
            }
            e += 4;
        }
        for (; e < end; e++) {
            int s = csr[e];
            uint2 v = t1h[(size_t)s * 32 + lane];
            float2 f0 = __half22float2(*(__half2*)&v.x);
            float2 f1 = __half22float2(*(__half2*)&v.y);
            a.x += f0.x; a.y += f0.y; a.z += f1.x; a.w += f1.y;
        }
        float r = g_rs_in[i];
        float4 y;
        y.x = a.x * r + bb.x;
        y.y = a.y * r + bb.y;
        y.z = a.z * r + bb.z;
        y.w = a.w * r + bb.w;
        ((float4*)g_y1)[(size_t)i * 32 + lane] = y;

        ls0 += y.x; lq0 += y.x * y.x;
        ls1 += y.y; lq1 += y.y * y.y;
        ls2 += y.z; lq2 += y.z * y.z;
        ls3 += y.w; lq3 += y.w * y.w;
    }
    int c = lane * 4;
    atomicAdd(&s_sum[c + 0], (double)ls0); atomicAdd(&s_sq[c + 0], (double)lq0);
    atomicAdd(&s_sum[c + 1], (double)ls1); atomicAdd(&s_sq[c + 1], (double)lq1);
    atomicAdd(&s_sum[c + 2], (double)ls2); atomicAdd(&s_sq[c + 2], (double)lq2);
    atomicAdd(&s_sum[c + 3], (double)ls3); atomicAdd(&s_sq[c + 3], (double)lq3);
    __syncthreads();
    if (tid < HID_DIM) {
        atomicAdd(&g_bnsum[tid], s_sum[tid]);
        atomicAdd(&g_bnsq [tid], s_sq [tid]);
    }
}

// ---------------------------------------------------------------------------
// 9. BN finalize: A = gamma*rsqrt(var+eps), B = beta - mean*A
// ---------------------------------------------------------------------------
__global__ void bn_finalize_kernel(const float* __restrict__ gamma,
                                   const float* __restrict__ beta,
                                   double invN) {
    int c = threadIdx.x;      // 128 threads
    double mean = g_bnsum[c] * invN;
    double var  = g_bnsq[c] * invN - mean * mean;
    float A = gamma[c] * rsqrtf((float)var + BN_EPS);
    g_A[c] = A;
    g_B[c] = beta[c] - (float)mean * A;
}

// ---------------------------------------------------------------------------
// 10. GEMM2: t2h = fp16( (relu(y1*A+B) * rs_out[:,None]) @ W2 )  [N,128]@[128,64]
//     BN + ReLU + degree-scale fused into the smem tile loader.
// ---------------------------------------------------------------------------
__global__ void gemm2_kernel(const float* __restrict__ W, int N) {
    extern __shared__ float smem[];
    float* Ws = smem;                 // 128*64
    float* Xs = smem + 128 * 64;      // 64*128
    int tid = threadIdx.x;

    const float4* W4 = (const float4*)W;
    float4* Ws4 = (float4*)Ws;
    #pragma unroll 4
    for (int i = tid; i < 128 * 64 / 4; i += 256) Ws4[i] = W4[i];

    int row0 = blockIdx.x * 64;
    float4* Xs4 = (float4*)Xs;
    for (int i = tid; i < 64 * 32; i += 256) {
        int r = i >> 5, c = i & 31;
        int row = row0 + r;
        float4 x = make_float4(0.f, 0.f, 0.f, 0.f);
        if (row < N) {
            float4 y  = ((const float4*)g_y1)[(size_t)row * 32 + c];
            float4 Av = ((const float4*)g_A)[c];
            float4 Bv = ((const float4*)g_B)[c];
            float s = g_rs_out[row];
            x.x = fmaxf(fmaf(y.x, Av.x, Bv.x), 0.f) * s;
            x.y = fmaxf(fmaf(y.y, Av.y, Bv.y), 0.f) * s;
            x.z = fmaxf(fmaf(y.z, Av.z, Bv.z), 0.f) * s;
            x.w = fmaxf(fmaf(y.w, Av.w, Bv.w), 0.f) * s;
        }
        Xs4[i] = x;
    }
    __syncthreads();

    int lane  = tid & 31;
    int rbase = (tid >> 5) * 8;
    float acc[8][2];
    #pragma unroll
    for (int r = 0; r < 8; r++) acc[r][0] = acc[r][1] = 0.f;

    for (int k = 0; k < 128; k += 4) {
        float4 xv[8];
        #pragma unroll
        for (int r = 0; r < 8; r++)
            xv[r] = *(const float4*)&Xs[(rbase + r) * 128 + k];
        #pragma unroll
        for (int kk = 0; kk < 4; kk++) {
            float2 wv = *(const float2*)&Ws[(k + kk) * 64 + lane * 2];
            #pragma unroll
            for (int r = 0; r < 8; r++) {
                float x = (kk == 0) ? xv[r].x : (kk == 1) ? xv[r].y
                        : (kk == 2) ? xv[r].z : xv[r].w;
                acc[r][0] = fmaf(x, wv.x, acc[r][0]);
                acc[r][1] = fmaf(x, wv.y, acc[r][1]);
            }
        }
    }
    #pragma unroll
    for (int r = 0; r < 8; r++) {
        int row = row0 + rbase + r;
        if (row < N) {
            __half2 p = __floats2half2_rn(acc[r][0], acc[r][1]);
            ((unsigned int*)g_t2h)[(size_t)row * 32 + lane] =
                *(unsigned int*)&p;
        }
    }
}

// ---------------------------------------------------------------------------
// 11. SpMM2: out[i] = (sum t2h[csr[e]]) * rs_in[i] + b2  (64-wide, fp16x2/lane)
//     8-deep load batching; fp32 accumulation.
// ---------------------------------------------------------------------------
__global__ void __launch_bounds__(256, 4)
spmm2_kernel(const float* __restrict__ b2,
             float* __restrict__ out, int N) {
    int tid = threadIdx.x;
    int lane = tid & 31;
    int gw = (blockIdx.x * blockDim.x + tid) >> 5;
    int nw = (gridDim.x * blockDim.x) >> 5;

    const unsigned int* __restrict__ t2h = (const unsigned int*)g_t2h;
    const int*          __restrict__ csr = g_csr;
    float2 bb = ((const float2*)b2)[lane];

    for (int i = gw; i < N; i += nw) {
        int beg = g_rowp[i], end = g_rowp[i + 1];
        float2 a = make_float2(0.f, 0.f);
        int e = beg;
        for (; e + 8 <= end; e += 8) {
            unsigned int v[8];
            #pragma unroll
            for (int j = 0; j < 8; j++) {
                int s = csr[e + j];
                v[j] = t2h[(size_t)s * 32 + lane];
            }
            #pragma unroll
            for (int j = 0; j < 8; j++) {
                float2 f = __half22float2(*(__half2*)&v[j]);
                a.x += f.x; a.y += f.y;
            }
        }
        if (e + 4 <= end) {
            unsigned int v[4];
            #pragma unroll
            for (int j = 0; j < 4; j++) {
                int s = csr[e + j];
                v[j] = t2h[(size_t)s * 32 + lane];
            }
            #pragma unroll
            for (int j = 0; j < 4; j++) {
                float2 f = __half22float2(*(__half2*)&v[j]);
                a.x += f.x; a.y += f.y;
            }
            e += 4;
        }
        for (; e < end; e++) {
            int s = csr[e];
            unsigned int v = t2h[(size_t)s * 32 + lane];
            float2 f = __half22float2(*(__half2*)&v);
            a.x += f.x; a.y += f.y;
        }
        float r = g_rs_in[i];
        float2 y;
        y.x = a.x * r + bb.x;
        y.y = a.y * r + bb.y;
        ((float2*)out)[(size_t)i * 32 + lane] = y;
    }
}

// ---------------------------------------------------------------------------
// Host launcher
// ---------------------------------------------------------------------------
extern "C" void kernel_launch(void* const* d_in, const int* in_sizes, int n_in,
                              void* d_out, int out_size) {
    const float* h     = (const float*)d_in[0];
    const float* W1    = (const float*)d_in[1];
    const float* b1    = (const float*)d_in[2];
    const float* W2    = (const float*)d_in[3];
    const float* b2    = (const float*)d_in[4];
    const float* gamma = (const float*)d_in[5];
    const float* beta  = (const float*)d_in[6];
    const int*   src   = (const int*)d_in[7];
    const int*   dst   = (const int*)d_in[8];

    int N = in_sizes[0] / IN_DIM;
    int E = in_sizes[7];
    if (N > MAXN || E > MAXE) return;  // shape is fixed; safety only

    // Opt-in dynamic smem (idempotent every call; not a stream op)
    cudaFuncSetAttribute(gemm1_kernel,
        cudaFuncAttributeMaxDynamicSharedMemorySize, (128*128 + 64*128) * 4);
    cudaFuncSetAttribute(gemm2_kernel,
        cudaFuncAttributeMaxDynamicSharedMemorySize, (128*64 + 64*128) * 4);

    int tb = 256;
    int nBlkN = (N + tb - 1) / tb;
    int nBlkE = (E + tb - 1) / tb;
    int nb = (N + 1023) / 1024;

    zero_kernel     <<<nBlkN, tb>>>(N);
    hist_kernel     <<<nBlkE, tb>>>(src, dst, E);
    scan_a_kernel   <<<nb, 1024>>>(N);
    scan_b_kernel   <<<1, 1024>>>(nb);
    scan_c_kernel   <<<nb, 1024>>>(N, E);
    csr_fill_kernel <<<nBlkE, tb>>>(src, dst, E);

    gemm1_kernel<<<(N + 63) / 64, 256, (128*128 + 64*128) * 4>>>(h, W1, N);
    spmm1_kernel<<<592, 256>>>(b1, N);
    bn_finalize_kernel<<<1, HID_DIM>>>(gamma, beta, 1.0 / (double)N);
    gemm2_kernel<<<(N + 63) / 64, 256, (128*64 + 64*128) * 4>>>(W2, N);
    spmm2_kernel<<<592, 256>>>(b2, (float*)d_out, N);
}